// round 10
// baseline (speedup 1.0000x reference)
#include <cuda_runtime.h>
#include <cuda_fp16.h>
#include <cstdint>

// ============================================================
// TorchRandomProject: out[4096,4096] = x[4096,2048] @ matrix[0][4096,2048]^T
// fp16 HMMA (same 10-bit mantissa as tf32 => same rel_err), fp32 accum.
// R10: R9 base (128x128, 2 CTA/SM, 3-stage, unroll-1 chunk loop) +
//  (a) dependency-ordered fragment loads (af0,bf0 first; bf1 mid-loop),
//  (b) cp.async spread 2-ops-per-kk-phase,
//  (c) per-CTA kk phase rotation (decorrelate co-resident CTAs).
// ============================================================

#define B_DIM   4096
#define K_DIM   2048
#define O_DIM   4096

// 32MB device scratch for fp16 operands
__device__ __half g_xh[(size_t)B_DIM * K_DIM];
__device__ __half g_wh[(size_t)O_DIM * K_DIM];

// ---------------- tile config ----------------
#define BM 128
#define BN 128
#define BK 64                       // K halfs per chunk (128B row)
#define NSTAGE 3
#define NCHUNK (K_DIM / BK)         // 32
#define A_BYTES (BM * BK * 2)       // 16384
#define B_BYTES (BN * BK * 2)       // 16384
#define STAGE_BYTES (A_BYTES + B_BYTES)      // 32768
#define SMEM_TOTAL (NSTAGE * STAGE_BYTES)    // 98304 (2 CTAs = 192KB/SM)

// ---------------- PTX helpers ----------------
__device__ __forceinline__ uint32_t smem_u32(const void* p) {
    uint32_t a;
    asm("{ .reg .u64 t; cvta.to.shared.u64 t, %1; cvt.u32.u64 %0, t; }" : "=r"(a) : "l"(p));
    return a;
}

__device__ __forceinline__ void cp_async16(uint32_t dst, const void* src) {
    asm volatile("cp.async.cg.shared.global [%0], [%1], 16;" :: "r"(dst), "l"(src) : "memory");
}
#define CP_COMMIT() asm volatile("cp.async.commit_group;" ::: "memory")
#define CP_WAIT(n)  asm volatile("cp.async.wait_group %0;" :: "n"(n) : "memory")

__device__ __forceinline__ void ldsm4(uint32_t r[4], uint32_t addr) {
    asm volatile("ldmatrix.sync.aligned.m8n8.x4.shared.b16 {%0,%1,%2,%3}, [%4];"
                 : "=r"(r[0]), "=r"(r[1]), "=r"(r[2]), "=r"(r[3]) : "r"(addr));
}

__device__ __forceinline__ void mma_f16(float c[4], const uint32_t a[4],
                                        uint32_t b0, uint32_t b1) {
    asm volatile(
        "mma.sync.aligned.m16n8k16.row.col.f32.f16.f16.f32 "
        "{%0,%1,%2,%3}, {%4,%5,%6,%7}, {%8,%9}, {%0,%1,%2,%3};"
        : "+f"(c[0]), "+f"(c[1]), "+f"(c[2]), "+f"(c[3])
        : "r"(a[0]), "r"(a[1]), "r"(a[2]), "r"(a[3]), "r"(b0), "r"(b1));
}

// ---------------- prep: fp32 -> fp16 (rne) ----------------
__global__ void cvt_f16_kernel(const float* __restrict__ x, const float* __restrict__ w) {
    size_t i = (size_t)blockIdx.x * blockDim.x + threadIdx.x;  // over 2M float4
    float4 a = reinterpret_cast<const float4*>(x)[i];
    reinterpret_cast<__half2*>(g_xh)[2 * i + 0] = __floats2half2_rn(a.x, a.y);
    reinterpret_cast<__half2*>(g_xh)[2 * i + 1] = __floats2half2_rn(a.z, a.w);
    float4 b = reinterpret_cast<const float4*>(w)[i];
    reinterpret_cast<__half2*>(g_wh)[2 * i + 0] = __floats2half2_rn(b.x, b.y);
    reinterpret_cast<__half2*>(g_wh)[2 * i + 1] = __floats2half2_rn(b.z, b.w);
}

// ---------------- GEMM ----------------
// smem per stage: A[128][64h] then B^T[128][64h], 128B rows, XOR-16B swizzle:
// 16B-chunk c of row r stored at chunk (c ^ (r & 7)).

// quarter-load: 2 cp.async ops per thread (half of one operand tile)
__device__ __forceinline__ void load_q2(int tid, uint32_t sdst,
                                        const __half* __restrict__ G,
                                        size_t koff, int qbase) {
#pragma unroll
    for (int q = 0; q < 2; q++) {            // 64 rows x 8 x 16B
        int idx = tid + (qbase + q) * 256;
        int row = idx >> 3, ch = idx & 7;
        uint32_t dst = sdst + (uint32_t)row * 128u + (uint32_t)((ch ^ (row & 7)) << 4);
        cp_async16(dst, G + (size_t)row * K_DIM + koff + ch * 8);
    }
}
__device__ __forceinline__ void load_half(int tid, uint32_t sdst,
                                          const __half* __restrict__ G,
                                          size_t koff) {
    load_q2(tid, sdst, G, koff, 0);
    load_q2(tid, sdst, G, koff, 2);
}

__global__ __launch_bounds__(256, 2) void gemm_f16_kernel(float* __restrict__ out) {
    extern __shared__ __align__(1024) char smem[];
    uint32_t sbase = smem_u32(smem);
    int tid  = threadIdx.x;
    int wid  = tid >> 5;
    int lane = tid & 31;
    int wm = wid >> 2;        // 0..1  -> M offset wm*64
    int wn = wid & 3;         // 0..3  -> N offset wn*32
    // kk rotation: SMSP partners (wid, wid+4) offset by 2; CTA id rotates too
    int bid = blockIdx.y * 32 + blockIdx.x;
    uint32_t woff = (uint32_t)((((wid & 3) + ((wid >> 2) << 1)) + bid) & 3);

    const __half* Ag = g_xh + (size_t)blockIdx.y * BM * K_DIM;
    const __half* Bg = g_wh + (size_t)blockIdx.x * BN * K_DIM;

    // ldmatrix address components (verified fragment mapping from R4-R9):
    uint32_t a_row[4], a_xor[4];
#pragma unroll
    for (int mt = 0; mt < 4; mt++) {
        int row = wm * 64 + mt * 16 + (lane & 15);
        a_row[mt] = (uint32_t)row * 128u;
        a_xor[mt] = (uint32_t)(row & 7);
    }
    uint32_t ahi = (uint32_t)(lane >> 4);
    uint32_t b_row[2], b_xor[2];
#pragma unroll
    for (int nt2 = 0; nt2 < 2; nt2++) {
        int row = wn * 32 + nt2 * 16 + (lane & 7) + ((lane >> 4) << 3);
        b_row[nt2] = (uint32_t)row * 128u;
        b_xor[nt2] = (uint32_t)(row & 7);
    }
    uint32_t bhi = (uint32_t)((lane >> 3) & 1);

    float acc[4][4][4];
#pragma unroll
    for (int mt = 0; mt < 4; mt++)
#pragma unroll
        for (int nt = 0; nt < 4; nt++)
#pragma unroll
            for (int r = 0; r < 4; r++) acc[mt][nt][r] = 0.0f;

    // prologue: chunks 0..NSTAGE-2
    load_half(tid, sbase + 0 * STAGE_BYTES, Ag, 0);
    load_half(tid, sbase + 0 * STAGE_BYTES + A_BYTES, Bg, 0);
    CP_COMMIT();
    load_half(tid, sbase + 1 * STAGE_BYTES, Ag, BK);
    load_half(tid, sbase + 1 * STAGE_BYTES + A_BYTES, Bg, BK);
    CP_COMMIT();

    // incremental stage offsets
    uint32_t soff_c = 0;                               // stage of chunk i
    uint32_t soff_l = (NSTAGE - 1) * STAGE_BYTES;      // stage of chunk i+2
    size_t   lkoff  = (size_t)(NSTAGE - 1) * BK;       // gmem K offset of load

#pragma unroll 1
    for (int i = 0; i < NCHUNK; i++) {
        CP_WAIT(1);                 // chunk i resident (uniform commit count)
        __syncthreads();            // RAW chunk i; WAR proof for stage (i+2)%3

        uint32_t sa = sbase + soff_c;
        uint32_t sb = sa + A_BYTES;
        uint32_t sl = sbase + soff_l;
        bool do_load = i < NCHUNK - (NSTAGE - 1);

#pragma unroll
        for (int kk2 = 0; kk2 < 4; kk2++) {    // 4 x k16, rotated per warp/CTA
            uint32_t kk = ((uint32_t)kk2 + woff) & 3u;
            uint32_t af[4][4], bf[2][4];
            // dependency-ordered loads: first mma needs af[0] + bf[0]
            ldsm4(af[0], sa + a_row[0] + (((2u * kk + ahi) ^ a_xor[0]) << 4));
            ldsm4(bf[0], sb + b_row[0] + (((2u * kk + bhi) ^ b_xor[0]) << 4));
            ldsm4(af[1], sa + a_row[1] + (((2u * kk + ahi) ^ a_xor[1]) << 4));
            ldsm4(af[2], sa + a_row[2] + (((2u * kk + ahi) ^ a_xor[2]) << 4));
            ldsm4(af[3], sa + a_row[3] + (((2u * kk + ahi) ^ a_xor[3]) << 4));

            // first n-half (nt = 0,1) uses bf[0] only
#pragma unroll
            for (int mt = 0; mt < 4; mt++)
                mma_f16(acc[mt][0], af[mt], bf[0][0], bf[0][1]);

            // interleave gmem->smem prefetch with tensor work (2 ops/phase)
            if (do_load) {
                if (kk2 == 0) load_q2(tid, sl, Ag, lkoff, 0);
                if (kk2 == 1) load_q2(tid, sl, Ag, lkoff, 2);
                if (kk2 == 2) load_q2(tid, sl + A_BYTES, Bg, lkoff, 0);
                if (kk2 == 3) load_q2(tid, sl + A_BYTES, Bg, lkoff, 2);
            }

            ldsm4(bf[1], sb + b_row[1] + (((2u * kk + bhi) ^ b_xor[1]) << 4));

#pragma unroll
            for (int mt = 0; mt < 4; mt++)
                mma_f16(acc[mt][1], af[mt], bf[0][2], bf[0][3]);
            // second n-half (nt = 2,3) uses bf[1]
#pragma unroll
            for (int mt = 0; mt < 4; mt++)
                mma_f16(acc[mt][2], af[mt], bf[1][0], bf[1][1]);
#pragma unroll
            for (int mt = 0; mt < 4; mt++)
                mma_f16(acc[mt][3], af[mt], bf[1][2], bf[1][3]);

            if (kk2 == 3) CP_COMMIT();   // uniform group count (empty if !do_load)
        }

        // advance stage ring
        soff_c += STAGE_BYTES; if (soff_c == NSTAGE * STAGE_BYTES) soff_c = 0;
        soff_l += STAGE_BYTES; if (soff_l == NSTAGE * STAGE_BYTES) soff_l = 0;
        lkoff  += BK;
    }

    // epilogue: direct STG from fragments (c0,c1 contiguous; c2,c3 at row+8)
    int g = lane >> 2, tig = lane & 3;
    size_t orow0 = (size_t)(blockIdx.y * BM + wm * 64 + g) * O_DIM;
    int ocol0 = blockIdx.x * BN + wn * 32 + 2 * tig;
#pragma unroll
    for (int mt = 0; mt < 4; mt++) {
#pragma unroll
        for (int nt = 0; nt < 4; nt++) {
            size_t base = orow0 + (size_t)(mt * 16) * O_DIM + (ocol0 + nt * 8);
            *reinterpret_cast<float2*>(out + base) =
                make_float2(acc[mt][nt][0], acc[mt][nt][1]);
            *reinterpret_cast<float2*>(out + base + (size_t)8 * O_DIM) =
                make_float2(acc[mt][nt][2], acc[mt][nt][3]);
        }
    }
}

// ---------------- launch ----------------
extern "C" void kernel_launch(void* const* d_in, const int* in_sizes, int n_in,
                              void* d_out, int out_size) {
    const float* x = (const float*)d_in[0];   // [4096, 2048]
    const float* w = (const float*)d_in[1];   // [1, 4096, 2048]
    float* out = (float*)d_out;               // [4096, 4096]

    // 1) round both operands to nearest-fp16 (same mantissa as tf32)
    cvt_f16_kernel<<<(B_DIM * K_DIM / 4) / 256, 256>>>(x, w);

    // 2) fp16 mma.sync GEMM, fp32 accumulate
    cudaFuncSetAttribute(gemm_f16_kernel, cudaFuncAttributeMaxDynamicSharedMemorySize,
                         SMEM_TOTAL);
    dim3 grid(O_DIM / BN, B_DIM / BM);        // (32, 32) = 1024 CTAs
    gemm_f16_kernel<<<grid, 256, SMEM_TOTAL>>>(out);
}